// round 11
// baseline (speedup 1.0000x reference)
#include <cuda_runtime.h>
#include <cuda_bf16.h>
#include <math.h>
#include <stdint.h>

#define BB 16
#define CC 128
#define HH 64
#define WW 64
#define NN 4096      // HH*WW
#define NHH 8
#define HDD 16
#define NHEADS 128   // BB*NHH
#define OUTC 512

// ---------------- scratch (static device globals; no allocation allowed) ----
__device__ float    g_qkv[BB * 3 * CC * NN];   // 100.7 MB : q|k|v (b, 384, n)
__device__ float    g_lambda[NHEADS * HDD * HDD];
__device__ float    g_pool[BB * CC];
__device__ float    g_pnum[NHEADS * 8 * 256];
__device__ float    g_pden[NHEADS * 8 * 16];
// packed bf16x2 operand planes (hi/lo split), pairs along K(channel)
__device__ uint32_t g_sh[BB * 64 * NN];        // 16.8 MB : CPE output (pairs)
__device__ uint32_t g_sl[BB * 64 * NN];
__device__ uint32_t g_xh[BB * 128 * NN];       // 33.5 MB : cat(r1, src*ca) pairs
__device__ uint32_t g_xl[BB * 128 * NN];
__device__ uint32_t g_wqh[64 * 384],  g_wql[64 * 384];   // qkv_w packed [k8][m]
__device__ uint32_t g_woh[128 * 512], g_wol[128 * 512];  // out_w packed [k8][m]

// ---------------------------------------------------------------------------
__device__ __forceinline__ void bf16_split2(float x0, float x1,
                                            uint32_t& hi, uint32_t& lo)
{
    __nv_bfloat16 h0 = __float2bfloat16_rn(x0);
    __nv_bfloat16 h1 = __float2bfloat16_rn(x1);
    __nv_bfloat16 l0 = __float2bfloat16_rn(x0 - __bfloat162float(h0));
    __nv_bfloat16 l1 = __float2bfloat16_rn(x1 - __bfloat162float(h1));
    hi = ((uint32_t)__bfloat16_as_ushort(h1) << 16) | __bfloat16_as_ushort(h0);
    lo = ((uint32_t)__bfloat16_as_ushort(l1) << 16) | __bfloat16_as_ushort(l0);
}

__device__ __forceinline__ void mma_bf16(float* d, const uint32_t* a, const uint32_t* b)
{
    asm volatile(
        "mma.sync.aligned.m16n8k16.row.col.f32.bf16.bf16.f32 "
        "{%0,%1,%2,%3}, {%4,%5,%6,%7}, {%8,%9}, {%0,%1,%2,%3};"
        : "+f"(d[0]), "+f"(d[1]), "+f"(d[2]), "+f"(d[3])
        : "r"(a[0]), "r"(a[1]), "r"(a[2]), "r"(a[3]), "r"(b[0]), "r"(b[1]));
}

__device__ __forceinline__ uint32_t smem_u32(const void* p) {
    uint32_t a;
    asm("{ .reg .u64 t; cvta.to.shared.u64 t, %1; cvt.u32.u64 %0, t; }"
        : "=r"(a) : "l"(p));
    return a;
}
#define CPA16(dst, src) \
    asm volatile("cp.async.cg.shared.global [%0], [%1], 16;" :: "r"(dst), "l"(src) : "memory")
#define CPA_COMMIT() asm volatile("cp.async.commit_group;" ::: "memory")

// ============================================================================
// K1: CPE dw3x3 + residual for a channel PAIR, fused pooling, packed output
// ============================================================================
__global__ __launch_bounds__(256) void cpe_pool_kernel(
    const float* __restrict__ src, const float* __restrict__ cpe_w)
{
    __shared__ float tile[2][HH][WW];   // 32 KB
    __shared__ float2 red[256];

    int cp = blockIdx.x, b = blockIdx.y;
    int c0 = cp * 2;
    int tid = threadIdx.x;
    const float* p0 = src + ((size_t)b * CC + c0) * NN;
    const float* p1 = p0 + NN;

    float s0 = 0.f, s1 = 0.f;
    #pragma unroll 4
    for (int i = tid; i < NN; i += 256) {
        float v0 = p0[i], v1 = p1[i];
        tile[0][i >> 6][i & 63] = v0;
        tile[1][i >> 6][i & 63] = v1;
        s0 += v0; s1 += v1;
    }
    red[tid] = make_float2(s0, s1);
    __syncthreads();
    for (int s = 128; s > 0; s >>= 1) {
        if (tid < s) {
            red[tid].x += red[tid + s].x;
            red[tid].y += red[tid + s].y;
        }
        __syncthreads();
    }
    if (tid == 0) {
        g_pool[b * CC + c0]     = red[0].x * (1.f / (float)NN);
        g_pool[b * CC + c0 + 1] = red[0].y * (1.f / (float)NN);
    }

    float w0[9], w1[9];
    #pragma unroll
    for (int j = 0; j < 9; j++) { w0[j] = cpe_w[c0 * 9 + j]; w1[j] = cpe_w[c0 * 9 + 9 + j]; }

    uint32_t* dh = g_sh + ((size_t)b * 64 + cp) * NN;
    uint32_t* dl = g_sl + ((size_t)b * 64 + cp) * NN;
    for (int i = tid; i < NN; i += 256) {
        int y = i >> 6, x = i & 63;
        float a0 = tile[0][y][x], a1 = tile[1][y][x];
        #pragma unroll
        for (int ky = 0; ky < 3; ky++) {
            int yy = y + ky - 1;
            if ((unsigned)yy >= HH) continue;
            #pragma unroll
            for (int kx = 0; kx < 3; kx++) {
                int xx = x + kx - 1;
                if ((unsigned)xx >= WW) continue;
                a0 += w0[ky * 3 + kx] * tile[0][yy][xx];
                a1 += w1[ky * 3 + kx] * tile[1][yy][xx];
            }
        }
        uint32_t hi, lo;
        bf16_split2(a0, a1, hi, lo);
        dh[i] = hi; dl[i] = lo;
    }
}

// ============================================================================
// K2: pack weights -> [k8][m] hi/lo planes
// ============================================================================
__global__ __launch_bounds__(256) void pack_w_kernel(
    const float* __restrict__ qkv_w, const float* __restrict__ out_w)
{
    int idx = blockIdx.x * 256 + threadIdx.x;
    if (idx < 64 * 384) {
        int k8 = idx / 384, m = idx % 384;
        float2 w2 = *(const float2*)&qkv_w[m * 128 + k8 * 2];
        bf16_split2(w2.x, w2.y, g_wqh[idx], g_wql[idx]);
    }
    int idx2 = idx - 64 * 384;
    if (idx2 >= 0 && idx2 < 128 * 512) {
        int k8 = idx2 / 512, m = idx2 % 512;
        float2 w2 = *(const float2*)&out_w[m * 256 + k8 * 2];
        bf16_split2(w2.x, w2.y, g_woh[idx2], g_wol[idx2]);
    }
}

// ============================================================================
// K3: pack src*ca into g_x rows 64..127 (ECA sigmoid computed inline)
// grid (64 cp, 16 b)
// ============================================================================
__global__ __launch_bounds__(256) void pack_src_kernel(
    const float* __restrict__ src, const float* __restrict__ conv1d_w)
{
    int cp = blockIdx.x, b = blockIdx.y;
    int tid = threadIdx.x;
    int c0 = cp * 2;
    const float* pp = g_pool + b * CC;
    float wA = conv1d_w[0], wB = conv1d_w[1], wCw = conv1d_w[2];
    float z0 = wA * ((c0 > 0) ? pp[c0 - 1] : 0.f) + wB * pp[c0] + wCw * pp[c0 + 1];
    float z1 = wA * pp[c0] + wB * pp[c0 + 1]
             + wCw * ((c0 + 2 < CC) ? pp[c0 + 2] : 0.f);
    float ca0 = 1.f / (1.f + __expf(-z0));
    float ca1 = 1.f / (1.f + __expf(-z1));

    const float* p0 = src + ((size_t)b * CC + c0) * NN;
    const float* p1 = p0 + NN;
    uint32_t* dh = g_xh + ((size_t)b * 128 + 64 + cp) * NN;
    uint32_t* dl = g_xl + ((size_t)b * 128 + 64 + cp) * NN;

    #pragma unroll
    for (int it = 0; it < 4; it++) {
        int i = (it * 256 + tid) * 4;
        float4 a = *(const float4*)&p0[i];
        float4 c4 = *(const float4*)&p1[i];
        uint4 h, l;
        bf16_split2(a.x * ca0, c4.x * ca1, h.x, l.x);
        bf16_split2(a.y * ca0, c4.y * ca1, h.y, l.y);
        bf16_split2(a.z * ca0, c4.z * ca1, h.z, l.z);
        bf16_split2(a.w * ca0, c4.w * ca1, h.w, l.w);
        *(uint4*)&dh[i] = h;
        *(uint4*)&dl[i] = l;
    }
}

// ============================================================================
// K4: unified split-bf16 GEMM; full-K B panel resident in smem, m-tile loop
// MODE 0: qkv  (M=384, K8=64,  NM=3, B=g_s*, C=g_qkv)
// MODE 1: out  (M=512, K8=128, NM=4, B=g_x*, C=Cout)
// grid (32 n-tiles, 1, 16 b), 256 thr
// ============================================================================
template<int MODE>
__global__ __launch_bounds__(256) void gemm_kernel(float* __restrict__ Cout)
{
    constexpr int M  = MODE ? 512 : 384;
    constexpr int K8 = MODE ? 128 : 64;
    constexpr int NC = K8 / 8;
    constexpr int NM = MODE ? 4 : 3;

    extern __shared__ uint32_t smem[];
    // layout: sBh[K8][132] | sBl[K8][132] | sAh[2][8][132] | sAl[2][8][132]
    uint32_t* sBh = smem;
    uint32_t* sBl = sBh + K8 * 132;
    uint32_t* sAh = sBl + K8 * 132;
    uint32_t* sAl = sAh + 2 * 8 * 132;

    const uint32_t* Ah = MODE ? g_woh : g_wqh;
    const uint32_t* Al = MODE ? g_wol : g_wql;

    int b  = blockIdx.z;
    int n0 = blockIdx.x * 128;

    const uint32_t* Bh = (MODE ? g_xh : g_sh) + (size_t)b * K8 * NN;
    const uint32_t* Bl = (MODE ? g_xl : g_sl) + (size_t)b * K8 * NN;
    float* C = MODE ? (Cout + (size_t)b * OUTC * NN)
                    : (g_qkv + (size_t)b * 3 * CC * NN);

    int tid  = threadIdx.x;
    int warp = tid >> 5, lane = tid & 31;
    int wm = (warp & 1) * 64;
    int wn = (warp >> 1) * 32;
    int gid = lane >> 2, tig = lane & 3;
    int arow = tid >> 5, aseg = tid & 31;

    // ---- load full B panel (K8 x 128 per plane)
    #pragma unroll
    for (int it = 0; it < K8 / 8; it++) {
        int idx = tid + it * 256;           // 0 .. K8*32-1
        int row = idx >> 5, seg = idx & 31;
        CPA16(smem_u32(&sBh[row * 132 + seg * 4]), Bh + (size_t)row * NN + n0 + seg * 4);
        CPA16(smem_u32(&sBl[row * 132 + seg * 4]), Bl + (size_t)row * NN + n0 + seg * 4);
    }
    CPA_COMMIT();
    asm volatile("cp.async.wait_group 0;" ::: "memory");
    __syncthreads();

    #pragma unroll 1
    for (int mt = 0; mt < NM; mt++) {
        int m0 = mt * 128;

        float acc[16][4];
        #pragma unroll
        for (int i = 0; i < 16; i++)
            #pragma unroll
            for (int j = 0; j < 4; j++) acc[i][j] = 0.f;

        // stage A chunk 0
        CPA16(smem_u32(&sAh[(0 * 8 + arow) * 132 + aseg * 4]),
              Ah + (size_t)arow * M + m0 + aseg * 4);
        CPA16(smem_u32(&sAl[(0 * 8 + arow) * 132 + aseg * 4]),
              Al + (size_t)arow * M + m0 + aseg * 4);
        CPA_COMMIT();

        #pragma unroll 1
        for (int c = 0; c < NC; c++) {
            if (c + 1 < NC) {
                int buf = (c + 1) & 1, k8 = (c + 1) * 8 + arow;
                CPA16(smem_u32(&sAh[(buf * 8 + arow) * 132 + aseg * 4]),
                      Ah + (size_t)k8 * M + m0 + aseg * 4);
                CPA16(smem_u32(&sAl[(buf * 8 + arow) * 132 + aseg * 4]),
                      Al + (size_t)k8 * M + m0 + aseg * 4);
                CPA_COMMIT();
                asm volatile("cp.async.wait_group 1;" ::: "memory");
            } else {
                asm volatile("cp.async.wait_group 0;" ::: "memory");
            }
            __syncthreads();

            int bf = c & 1;
            const uint32_t* pAh = sAh + bf * 8 * 132;
            const uint32_t* pAl = sAl + bf * 8 * 132;
            const uint32_t* pBh = sBh + c * 8 * 132;
            const uint32_t* pBl = sBl + c * 8 * 132;

            uint32_t ah[4][4], al[4][4], bh[4][2], bl[4][2];
            #pragma unroll
            for (int am = 0; am < 4; am++) {
                int mr = wm + am * 16 + gid;
                ah[am][0] = pAh[tig * 132 + mr];           al[am][0] = pAl[tig * 132 + mr];
                ah[am][1] = pAh[tig * 132 + mr + 8];       al[am][1] = pAl[tig * 132 + mr + 8];
                ah[am][2] = pAh[(tig + 4) * 132 + mr];     al[am][2] = pAl[(tig + 4) * 132 + mr];
                ah[am][3] = pAh[(tig + 4) * 132 + mr + 8]; al[am][3] = pAl[(tig + 4) * 132 + mr + 8];
            }
            #pragma unroll
            for (int an = 0; an < 4; an++) {
                int nc = wn + an * 8 + gid;
                bh[an][0] = pBh[tig * 132 + nc];       bl[an][0] = pBl[tig * 132 + nc];
                bh[an][1] = pBh[(tig + 4) * 132 + nc]; bl[an][1] = pBl[(tig + 4) * 132 + nc];
            }
            #pragma unroll
            for (int am = 0; am < 4; am++)
                #pragma unroll
                for (int an = 0; an < 4; an++) {
                    float* d = acc[am * 4 + an];
                    mma_bf16(d, ah[am], bh[an]);
                    mma_bf16(d, al[am], bh[an]);
                    mma_bf16(d, ah[am], bl[an]);
                }
            __syncthreads();
        }

        #pragma unroll
        for (int am = 0; am < 4; am++)
            #pragma unroll
            for (int an = 0; an < 4; an++) {
                const float* d = acc[am * 4 + an];
                int row = m0 + wm + am * 16 + gid;
                int col = n0 + wn + an * 8 + 2 * tig;
                float* dst = C + (size_t)row * NN + col;
                *(float2*)dst            = make_float2(d[0], d[1]);
                *(float2*)(dst + 8 * NN) = make_float2(d[2], d[3]);
            }
    }
}

#define GSMEM(MODE) (((MODE ? 128 : 64) * 132 * 2 + 2 * 8 * 132 * 2) * 4)

// ============================================================================
// K5: partial lambda over N-chunks (no max subtraction; k is O(10) bounded)
// ============================================================================
__global__ __launch_bounds__(256) void lambda_part_kernel()
{
    int ch = blockIdx.x, h = blockIdx.y;
    int b = h >> 3, nh = h & 7;
    int warp = threadIdx.x >> 5, lane = threadIdx.x & 31;
    int i0 = warp * 2;

    const float* kbase = g_qkv + (size_t)(b * 384 + 128 + nh * 16) * NN;
    const float* vbase = g_qkv + (size_t)(b * 384 + 256 + nh * 16) * NN;
    const float* k0p = kbase + (size_t)i0 * NN;
    const float* k1p = k0p + NN;

    float acc0[16], acc1[16], s0 = 0.f, s1 = 0.f;
    #pragma unroll
    for (int o = 0; o < 16; o++) { acc0[o] = 0.f; acc1[o] = 0.f; }

    int nbeg = ch * 512 + lane;
    #pragma unroll 2
    for (int it = 0; it < 16; it++) {
        int n = nbeg + it * 32;
        float p0 = __expf(k0p[n]);
        float p1 = __expf(k1p[n]);
        s0 += p0; s1 += p1;
        #pragma unroll
        for (int o = 0; o < 16; o++) {
            float vv = vbase[(size_t)o * NN + n];
            acc0[o] += p0 * vv;
            acc1[o] += p1 * vv;
        }
    }
    #pragma unroll
    for (int off = 16; off; off >>= 1) {
        s0 += __shfl_xor_sync(0xffffffffu, s0, off);
        s1 += __shfl_xor_sync(0xffffffffu, s1, off);
        #pragma unroll
        for (int o = 0; o < 16; o++) {
            acc0[o] += __shfl_xor_sync(0xffffffffu, acc0[o], off);
            acc1[o] += __shfl_xor_sync(0xffffffffu, acc1[o], off);
        }
    }
    if (lane == 0) {
        float* pn = g_pnum + (size_t)(h * 8 + ch) * 256;
        #pragma unroll
        for (int o = 0; o < 16; o++) {
            pn[i0 * 16 + o]       = acc0[o];
            pn[(i0 + 1) * 16 + o] = acc1[o];
        }
        g_pden[(h * 8 + ch) * 16 + i0]     = s0;
        g_pden[(h * 8 + ch) * 16 + i0 + 1] = s1;
    }
}

// ============================================================================
// K6: combine partials -> lambda (0.25 scaling folded)
// ============================================================================
__global__ __launch_bounds__(256) void lambda_comb_kernel()
{
    int h = blockIdx.x, t = threadIdx.x;
    int i = t >> 4;
    float num = 0.f, den = 0.f;
    #pragma unroll
    for (int ch = 0; ch < 8; ch++) {
        num += g_pnum[(size_t)(h * 8 + ch) * 256 + t];
        den += g_pden[(h * 8 + ch) * 16 + i];
    }
    g_lambda[h * 256 + t] = 0.25f * num / den;
}

// ============================================================================
// K7: result1 = content + q * dwconv5x5(v), packed bf16 pair output
// ============================================================================
__global__ __launch_bounds__(256) void attn_out_kernel(const float* __restrict__ rel_pos)
{
    __shared__ float vs[16][20][20];
    __shared__ float ls[16][16];
    __shared__ float rw[16][25];

    int h = blockIdx.z;
    int b = h >> 3, nh = h & 7;
    int x0 = blockIdx.x * 16, y0 = blockIdx.y * 16;

    const float* vbase = g_qkv + (size_t)(b * 384 + 256 + nh * 16) * NN;
    const float* qbase = g_qkv + (size_t)(b * 384 +   0 + nh * 16) * NN;

    int tid = threadIdx.x;
    int tx = tid & 15, ty = tid >> 4;

    ls[tid >> 4][tid & 15] = g_lambda[h * 256 + tid];
    for (int i = tid; i < 400; i += 256) rw[i / 25][i % 25] = rel_pos[i];

    for (int i = tid; i < 16 * 400; i += 256) {
        int chn = i / 400, r = i % 400;
        int yy = y0 + r / 20 - 2, xx = x0 + (r % 20) - 2;
        float val = 0.f;
        if ((unsigned)yy < HH && (unsigned)xx < WW)
            val = vbase[(size_t)chn * NN + yy * 64 + xx];
        vs[chn][r / 20][r % 20] = val;
    }
    __syncthreads();

    int y = y0 + ty, x = x0 + tx;
    int n = y * 64 + x;

    float q[16];
    #pragma unroll
    for (int i = 0; i < 16; i++) q[i] = qbase[(size_t)i * NN + n];

    float res[16];
    #pragma unroll
    for (int o = 0; o < 16; o++) {
        float cont = 0.f;
        #pragma unroll
        for (int i = 0; i < 16; i++) cont += q[i] * ls[i][o];
        float pos = 0.f;
        #pragma unroll
        for (int ky = 0; ky < 5; ky++)
            #pragma unroll
            for (int kx = 0; kx < 5; kx++)
                pos += rw[o][ky * 5 + kx] * vs[o][ty + ky][tx + kx];
        res[o] = cont + q[o] * pos;
    }

    uint32_t* xh = g_xh + ((size_t)b * 128 + nh * 8) * NN + n;
    uint32_t* xl = g_xl + ((size_t)b * 128 + nh * 8) * NN + n;
    #pragma unroll
    for (int o2 = 0; o2 < 8; o2++) {
        uint32_t hi, lo;
        bf16_split2(res[2 * o2], res[2 * o2 + 1], hi, lo);
        xh[(size_t)o2 * NN] = hi;
        xl[(size_t)o2 * NN] = lo;
    }
}

// ============================================================================
extern "C" void kernel_launch(void* const* d_in, const int* in_sizes, int n_in,
                              void* d_out, int out_size)
{
    const float* src      = (const float*)d_in[0];  // (16,128,64,64)
    const float* cpe_w    = (const float*)d_in[1];  // (128,1,3,3)
    const float* qkv_w    = (const float*)d_in[2];  // (384,128)
    const float* rel_pos  = (const float*)d_in[3];  // (16,5,5)
    const float* conv1d_w = (const float*)d_in[4];  // (3,)
    const float* out_w    = (const float*)d_in[5];  // (512,256)
    float* out = (float*)d_out;                     // (16,512,64,64)

    static int attr_set = 0;
    if (!attr_set) {
        cudaFuncSetAttribute(gemm_kernel<0>,
            cudaFuncAttributeMaxDynamicSharedMemorySize, GSMEM(0));
        cudaFuncSetAttribute(gemm_kernel<1>,
            cudaFuncAttributeMaxDynamicSharedMemorySize, GSMEM(1));
        attr_set = 1;
    }

    pack_w_kernel<<<(64 * 384 + 128 * 512 + 255) / 256, 256>>>(qkv_w, out_w);
    cpe_pool_kernel<<<dim3(64, BB), 256>>>(src, cpe_w);
    pack_src_kernel<<<dim3(64, BB), 256>>>(src, conv1d_w);
    gemm_kernel<0><<<dim3(32, 1, BB), 256, GSMEM(0)>>>(nullptr);
    lambda_part_kernel<<<dim3(8, NHEADS), 256>>>();
    lambda_comb_kernel<<<NHEADS, 256>>>();
    attn_out_kernel<<<dim3(4, 4, NHEADS), 256>>>(rel_pos);
    gemm_kernel<1><<<dim3(32, 1, BB), 256, GSMEM(1)>>>(out);
}

// round 13
// speedup vs baseline: 1.2023x; 1.2023x over previous
#include <cuda_runtime.h>
#include <cuda_bf16.h>
#include <math.h>
#include <stdint.h>

#define BB 16
#define CC 128
#define HH 64
#define WW 64
#define NN 4096      // HH*WW
#define NHH 8
#define HDD 16
#define NHEADS 128   // BB*NHH
#define OUTC 512

// ---------------- scratch (static device globals; no allocation allowed) ----
__device__ float    g_qkv[BB * 3 * CC * NN];   // 100.7 MB : q|k|v (b, 384, n)
__device__ float    g_lambda[NHEADS * HDD * HDD];
__device__ float    g_pool[BB * CC];
__device__ float    g_pnum[NHEADS * 8 * 256];
__device__ float    g_pden[NHEADS * 8 * 16];
// packed bf16x2 operand planes (hi/lo split), pairs along K(channel)
__device__ uint32_t g_sh[BB * 64 * NN];        // 16.8 MB : CPE output (pairs)
__device__ uint32_t g_sl[BB * 64 * NN];
__device__ uint32_t g_xh[BB * 128 * NN];       // 33.5 MB : cat(r1, src*ca) pairs
__device__ uint32_t g_xl[BB * 128 * NN];
__device__ uint32_t g_wqh[64 * 384],  g_wql[64 * 384];   // qkv_w packed [k8][m]
__device__ uint32_t g_woh[128 * 512], g_wol[128 * 512];  // out_w packed [k8][m]

// ---------------------------------------------------------------------------
__device__ __forceinline__ void bf16_split2(float x0, float x1,
                                            uint32_t& hi, uint32_t& lo)
{
    __nv_bfloat16 h0 = __float2bfloat16_rn(x0);
    __nv_bfloat16 h1 = __float2bfloat16_rn(x1);
    __nv_bfloat16 l0 = __float2bfloat16_rn(x0 - __bfloat162float(h0));
    __nv_bfloat16 l1 = __float2bfloat16_rn(x1 - __bfloat162float(h1));
    hi = ((uint32_t)__bfloat16_as_ushort(h1) << 16) | __bfloat16_as_ushort(h0);
    lo = ((uint32_t)__bfloat16_as_ushort(l1) << 16) | __bfloat16_as_ushort(l0);
}

__device__ __forceinline__ void mma_bf16(float* d, const uint32_t* a, const uint32_t* b)
{
    asm volatile(
        "mma.sync.aligned.m16n8k16.row.col.f32.bf16.bf16.f32 "
        "{%0,%1,%2,%3}, {%4,%5,%6,%7}, {%8,%9}, {%0,%1,%2,%3};"
        : "+f"(d[0]), "+f"(d[1]), "+f"(d[2]), "+f"(d[3])
        : "r"(a[0]), "r"(a[1]), "r"(a[2]), "r"(a[3]), "r"(b[0]), "r"(b[1]));
}

__device__ __forceinline__ uint32_t smem_u32(const void* p) {
    uint32_t a;
    asm("{ .reg .u64 t; cvta.to.shared.u64 t, %1; cvt.u32.u64 %0, t; }"
        : "=r"(a) : "l"(p));
    return a;
}
#define CPA16(dst, src) \
    asm volatile("cp.async.cg.shared.global [%0], [%1], 16;" :: "r"(dst), "l"(src) : "memory")
#define CPA_COMMIT() asm volatile("cp.async.commit_group;" ::: "memory")

// ============================================================================
// K1: CPE dw3x3 + residual for a channel PAIR, fused pooling, packed output
// ============================================================================
__global__ __launch_bounds__(256) void cpe_pool_kernel(
    const float* __restrict__ src, const float* __restrict__ cpe_w)
{
    __shared__ float tile[2][HH][WW];   // 32 KB
    __shared__ float2 red[256];

    int cp = blockIdx.x, b = blockIdx.y;
    int c0 = cp * 2;
    int tid = threadIdx.x;
    const float* p0 = src + ((size_t)b * CC + c0) * NN;
    const float* p1 = p0 + NN;

    float s0 = 0.f, s1 = 0.f;
    #pragma unroll 4
    for (int i = tid; i < NN; i += 256) {
        float v0 = p0[i], v1 = p1[i];
        tile[0][i >> 6][i & 63] = v0;
        tile[1][i >> 6][i & 63] = v1;
        s0 += v0; s1 += v1;
    }
    red[tid] = make_float2(s0, s1);
    __syncthreads();
    for (int s = 128; s > 0; s >>= 1) {
        if (tid < s) {
            red[tid].x += red[tid + s].x;
            red[tid].y += red[tid + s].y;
        }
        __syncthreads();
    }
    if (tid == 0) {
        g_pool[b * CC + c0]     = red[0].x * (1.f / (float)NN);
        g_pool[b * CC + c0 + 1] = red[0].y * (1.f / (float)NN);
    }

    float w0[9], w1[9];
    #pragma unroll
    for (int j = 0; j < 9; j++) { w0[j] = cpe_w[c0 * 9 + j]; w1[j] = cpe_w[c0 * 9 + 9 + j]; }

    uint32_t* dh = g_sh + ((size_t)b * 64 + cp) * NN;
    uint32_t* dl = g_sl + ((size_t)b * 64 + cp) * NN;
    for (int i = tid; i < NN; i += 256) {
        int y = i >> 6, x = i & 63;
        float a0 = tile[0][y][x], a1 = tile[1][y][x];
        #pragma unroll
        for (int ky = 0; ky < 3; ky++) {
            int yy = y + ky - 1;
            if ((unsigned)yy >= HH) continue;
            #pragma unroll
            for (int kx = 0; kx < 3; kx++) {
                int xx = x + kx - 1;
                if ((unsigned)xx >= WW) continue;
                a0 += w0[ky * 3 + kx] * tile[0][yy][xx];
                a1 += w1[ky * 3 + kx] * tile[1][yy][xx];
            }
        }
        uint32_t hi, lo;
        bf16_split2(a0, a1, hi, lo);
        dh[i] = hi; dl[i] = lo;
    }
}

// ============================================================================
// K2: pack weights -> [k8][m] hi/lo planes
// ============================================================================
__global__ __launch_bounds__(256) void pack_w_kernel(
    const float* __restrict__ qkv_w, const float* __restrict__ out_w)
{
    int idx = blockIdx.x * 256 + threadIdx.x;
    if (idx < 64 * 384) {
        int k8 = idx / 384, m = idx % 384;
        float2 w2 = *(const float2*)&qkv_w[m * 128 + k8 * 2];
        bf16_split2(w2.x, w2.y, g_wqh[idx], g_wql[idx]);
    }
    int idx2 = idx - 64 * 384;
    if (idx2 >= 0 && idx2 < 128 * 512) {
        int k8 = idx2 / 512, m = idx2 % 512;
        float2 w2 = *(const float2*)&out_w[m * 256 + k8 * 2];
        bf16_split2(w2.x, w2.y, g_woh[idx2], g_wol[idx2]);
    }
}

// ============================================================================
// K3: pack src*ca into g_x rows 64..127 (ECA sigmoid computed inline)
// grid (64 cp, 16 b)
// ============================================================================
__global__ __launch_bounds__(256) void pack_src_kernel(
    const float* __restrict__ src, const float* __restrict__ conv1d_w)
{
    int cp = blockIdx.x, b = blockIdx.y;
    int tid = threadIdx.x;
    int c0 = cp * 2;
    const float* pp = g_pool + b * CC;
    float wA = conv1d_w[0], wB = conv1d_w[1], wCw = conv1d_w[2];
    float z0 = wA * ((c0 > 0) ? pp[c0 - 1] : 0.f) + wB * pp[c0] + wCw * pp[c0 + 1];
    float z1 = wA * pp[c0] + wB * pp[c0 + 1]
             + wCw * ((c0 + 2 < CC) ? pp[c0 + 2] : 0.f);
    float ca0 = 1.f / (1.f + __expf(-z0));
    float ca1 = 1.f / (1.f + __expf(-z1));

    const float* p0 = src + ((size_t)b * CC + c0) * NN;
    const float* p1 = p0 + NN;
    uint32_t* dh = g_xh + ((size_t)b * 128 + 64 + cp) * NN;
    uint32_t* dl = g_xl + ((size_t)b * 128 + 64 + cp) * NN;

    #pragma unroll
    for (int it = 0; it < 4; it++) {
        int i = (it * 256 + tid) * 4;
        float4 a = *(const float4*)&p0[i];
        float4 c4 = *(const float4*)&p1[i];
        uint4 h, l;
        bf16_split2(a.x * ca0, c4.x * ca1, h.x, l.x);
        bf16_split2(a.y * ca0, c4.y * ca1, h.y, l.y);
        bf16_split2(a.z * ca0, c4.z * ca1, h.z, l.z);
        bf16_split2(a.w * ca0, c4.w * ca1, h.w, l.w);
        *(uint4*)&dh[i] = h;
        *(uint4*)&dl[i] = l;
    }
}

// ============================================================================
// K4: unified split-bf16 GEMM, cp.async double-buffered (R10 structure)
// grid (NM m-tiles [fastest], 32 n-tiles, 16 b) -> consecutive CTAs share the
// same B n-strip so redundant B reads hit L2.
// MODE 0: qkv  (M=384, K8=64,  B=g_s*, C=g_qkv)
// MODE 1: out  (M=512, K8=128, B=g_x*, C=Cout)
// ============================================================================
template<int MODE>
__global__ __launch_bounds__(256) void gemm_kernel(float* __restrict__ Cout)
{
    constexpr int M  = MODE ? 512 : 384;
    constexpr int K8 = MODE ? 128 : 64;
    constexpr int NC = K8 / 8;

    __shared__ uint32_t sAh[2][8][132], sAl[2][8][132];
    __shared__ uint32_t sBh[2][8][132], sBl[2][8][132];

    const uint32_t* Ah = MODE ? g_woh : g_wqh;
    const uint32_t* Al = MODE ? g_wol : g_wql;

    int b  = blockIdx.z;
    int m0 = blockIdx.x * 128;      // m fastest -> B strip shared by adjacent CTAs
    int n0 = blockIdx.y * 128;

    const uint32_t* Bh = (MODE ? g_xh : g_sh) + (size_t)b * K8 * NN;
    const uint32_t* Bl = (MODE ? g_xl : g_sl) + (size_t)b * K8 * NN;
    float* C = MODE ? (Cout + (size_t)b * OUTC * NN)
                    : (g_qkv + (size_t)b * 3 * CC * NN);

    int tid  = threadIdx.x;
    int warp = tid >> 5, lane = tid & 31;
    int wm = (warp & 1) * 64;
    int wn = (warp >> 1) * 32;
    int gid = lane >> 2, tig = lane & 3;
    int arow = tid >> 5, aseg = tid & 31;   // stage mapping: 8 rows x 32 segs

    float acc[16][4];
    #pragma unroll
    for (int i = 0; i < 16; i++)
        #pragma unroll
        for (int j = 0; j < 4; j++) acc[i][j] = 0.f;

    // ---- stage chunk 0
    {
        int k8 = arow;
        CPA16(smem_u32(&sAh[0][arow][aseg * 4]), Ah + (size_t)k8 * M + m0 + aseg * 4);
        CPA16(smem_u32(&sAl[0][arow][aseg * 4]), Al + (size_t)k8 * M + m0 + aseg * 4);
        CPA16(smem_u32(&sBh[0][arow][aseg * 4]), Bh + (size_t)k8 * NN + n0 + aseg * 4);
        CPA16(smem_u32(&sBl[0][arow][aseg * 4]), Bl + (size_t)k8 * NN + n0 + aseg * 4);
        CPA_COMMIT();
    }

    #pragma unroll 1
    for (int c = 0; c < NC; c++) {
        if (c + 1 < NC) {
            int buf = (c + 1) & 1, k8 = (c + 1) * 8 + arow;
            CPA16(smem_u32(&sAh[buf][arow][aseg * 4]), Ah + (size_t)k8 * M + m0 + aseg * 4);
            CPA16(smem_u32(&sAl[buf][arow][aseg * 4]), Al + (size_t)k8 * M + m0 + aseg * 4);
            CPA16(smem_u32(&sBh[buf][arow][aseg * 4]), Bh + (size_t)k8 * NN + n0 + aseg * 4);
            CPA16(smem_u32(&sBl[buf][arow][aseg * 4]), Bl + (size_t)k8 * NN + n0 + aseg * 4);
            CPA_COMMIT();
            asm volatile("cp.async.wait_group 1;" ::: "memory");
        } else {
            asm volatile("cp.async.wait_group 0;" ::: "memory");
        }
        __syncthreads();

        int bf = c & 1;
        uint32_t ah[4][4], al[4][4], bh[4][2], bl[4][2];
        #pragma unroll
        for (int am = 0; am < 4; am++) {
            int mr = wm + am * 16 + gid;
            ah[am][0] = sAh[bf][tig][mr];     al[am][0] = sAl[bf][tig][mr];
            ah[am][1] = sAh[bf][tig][mr + 8]; al[am][1] = sAl[bf][tig][mr + 8];
            ah[am][2] = sAh[bf][tig + 4][mr];     al[am][2] = sAl[bf][tig + 4][mr];
            ah[am][3] = sAh[bf][tig + 4][mr + 8]; al[am][3] = sAl[bf][tig + 4][mr + 8];
        }
        #pragma unroll
        for (int an = 0; an < 4; an++) {
            int nc = wn + an * 8 + gid;
            bh[an][0] = sBh[bf][tig][nc];     bl[an][0] = sBl[bf][tig][nc];
            bh[an][1] = sBh[bf][tig + 4][nc]; bl[an][1] = sBl[bf][tig + 4][nc];
        }
        #pragma unroll
        for (int am = 0; am < 4; am++)
            #pragma unroll
            for (int an = 0; an < 4; an++) {
                float* d = acc[am * 4 + an];
                mma_bf16(d, ah[am], bh[an]);
                mma_bf16(d, al[am], bh[an]);
                mma_bf16(d, ah[am], bl[an]);
            }
        __syncthreads();
    }

    #pragma unroll
    for (int am = 0; am < 4; am++)
        #pragma unroll
        for (int an = 0; an < 4; an++) {
            const float* d = acc[am * 4 + an];
            int row = m0 + wm + am * 16 + gid;
            int col = n0 + wn + an * 8 + 2 * tig;
            float* dst = C + (size_t)row * NN + col;
            *(float2*)dst            = make_float2(d[0], d[1]);
            *(float2*)(dst + 8 * NN) = make_float2(d[2], d[3]);
        }
}

// ============================================================================
// K5: partial lambda over N-chunks (no max subtraction; k is O(10) bounded)
// ============================================================================
__global__ __launch_bounds__(256) void lambda_part_kernel()
{
    int ch = blockIdx.x, h = blockIdx.y;
    int b = h >> 3, nh = h & 7;
    int warp = threadIdx.x >> 5, lane = threadIdx.x & 31;
    int i0 = warp * 2;

    const float* kbase = g_qkv + (size_t)(b * 384 + 128 + nh * 16) * NN;
    const float* vbase = g_qkv + (size_t)(b * 384 + 256 + nh * 16) * NN;
    const float* k0p = kbase + (size_t)i0 * NN;
    const float* k1p = k0p + NN;

    float acc0[16], acc1[16], s0 = 0.f, s1 = 0.f;
    #pragma unroll
    for (int o = 0; o < 16; o++) { acc0[o] = 0.f; acc1[o] = 0.f; }

    int nbeg = ch * 512 + lane;
    #pragma unroll 2
    for (int it = 0; it < 16; it++) {
        int n = nbeg + it * 32;
        float p0 = __expf(k0p[n]);
        float p1 = __expf(k1p[n]);
        s0 += p0; s1 += p1;
        #pragma unroll
        for (int o = 0; o < 16; o++) {
            float vv = vbase[(size_t)o * NN + n];
            acc0[o] += p0 * vv;
            acc1[o] += p1 * vv;
        }
    }
    #pragma unroll
    for (int off = 16; off; off >>= 1) {
        s0 += __shfl_xor_sync(0xffffffffu, s0, off);
        s1 += __shfl_xor_sync(0xffffffffu, s1, off);
        #pragma unroll
        for (int o = 0; o < 16; o++) {
            acc0[o] += __shfl_xor_sync(0xffffffffu, acc0[o], off);
            acc1[o] += __shfl_xor_sync(0xffffffffu, acc1[o], off);
        }
    }
    if (lane == 0) {
        float* pn = g_pnum + (size_t)(h * 8 + ch) * 256;
        #pragma unroll
        for (int o = 0; o < 16; o++) {
            pn[i0 * 16 + o]       = acc0[o];
            pn[(i0 + 1) * 16 + o] = acc1[o];
        }
        g_pden[(h * 8 + ch) * 16 + i0]     = s0;
        g_pden[(h * 8 + ch) * 16 + i0 + 1] = s1;
    }
}

// ============================================================================
// K6: combine partials -> lambda (0.25 scaling folded)
// ============================================================================
__global__ __launch_bounds__(256) void lambda_comb_kernel()
{
    int h = blockIdx.x, t = threadIdx.x;
    int i = t >> 4;
    float num = 0.f, den = 0.f;
    #pragma unroll
    for (int ch = 0; ch < 8; ch++) {
        num += g_pnum[(size_t)(h * 8 + ch) * 256 + t];
        den += g_pden[(h * 8 + ch) * 16 + i];
    }
    g_lambda[h * 256 + t] = 0.25f * num / den;
}

// ============================================================================
// K7: result1 = content + q * dwconv5x5(v), packed bf16 pair output
// ============================================================================
__global__ __launch_bounds__(256) void attn_out_kernel(const float* __restrict__ rel_pos)
{
    __shared__ float vs[16][20][20];
    __shared__ float ls[16][16];
    __shared__ float rw[16][25];

    int h = blockIdx.z;
    int b = h >> 3, nh = h & 7;
    int x0 = blockIdx.x * 16, y0 = blockIdx.y * 16;

    const float* vbase = g_qkv + (size_t)(b * 384 + 256 + nh * 16) * NN;
    const float* qbase = g_qkv + (size_t)(b * 384 +   0 + nh * 16) * NN;

    int tid = threadIdx.x;
    int tx = tid & 15, ty = tid >> 4;

    ls[tid >> 4][tid & 15] = g_lambda[h * 256 + tid];
    for (int i = tid; i < 400; i += 256) rw[i / 25][i % 25] = rel_pos[i];

    for (int i = tid; i < 16 * 400; i += 256) {
        int chn = i / 400, r = i % 400;
        int yy = y0 + r / 20 - 2, xx = x0 + (r % 20) - 2;
        float val = 0.f;
        if ((unsigned)yy < HH && (unsigned)xx < WW)
            val = vbase[(size_t)chn * NN + yy * 64 + xx];
        vs[chn][r / 20][r % 20] = val;
    }
    __syncthreads();

    int y = y0 + ty, x = x0 + tx;
    int n = y * 64 + x;

    float q[16];
    #pragma unroll
    for (int i = 0; i < 16; i++) q[i] = qbase[(size_t)i * NN + n];

    float res[16];
    #pragma unroll
    for (int o = 0; o < 16; o++) {
        float cont = 0.f;
        #pragma unroll
        for (int i = 0; i < 16; i++) cont += q[i] * ls[i][o];
        float pos = 0.f;
        #pragma unroll
        for (int ky = 0; ky < 5; ky++)
            #pragma unroll
            for (int kx = 0; kx < 5; kx++)
                pos += rw[o][ky * 5 + kx] * vs[o][ty + ky][tx + kx];
        res[o] = cont + q[o] * pos;
    }

    uint32_t* xh = g_xh + ((size_t)b * 128 + nh * 8) * NN + n;
    uint32_t* xl = g_xl + ((size_t)b * 128 + nh * 8) * NN + n;
    #pragma unroll
    for (int o2 = 0; o2 < 8; o2++) {
        uint32_t hi, lo;
        bf16_split2(res[2 * o2], res[2 * o2 + 1], hi, lo);
        xh[(size_t)o2 * NN] = hi;
        xl[(size_t)o2 * NN] = lo;
    }
}

// ============================================================================
extern "C" void kernel_launch(void* const* d_in, const int* in_sizes, int n_in,
                              void* d_out, int out_size)
{
    const float* src      = (const float*)d_in[0];  // (16,128,64,64)
    const float* cpe_w    = (const float*)d_in[1];  // (128,1,3,3)
    const float* qkv_w    = (const float*)d_in[2];  // (384,128)
    const float* rel_pos  = (const float*)d_in[3];  // (16,5,5)
    const float* conv1d_w = (const float*)d_in[4];  // (3,)
    const float* out_w    = (const float*)d_in[5];  // (512,256)
    float* out = (float*)d_out;                     // (16,512,64,64)

    pack_w_kernel<<<(64 * 384 + 128 * 512 + 255) / 256, 256>>>(qkv_w, out_w);
    cpe_pool_kernel<<<dim3(64, BB), 256>>>(src, cpe_w);
    pack_src_kernel<<<dim3(64, BB), 256>>>(src, conv1d_w);
    gemm_kernel<0><<<dim3(3, 32, BB), 256>>>(nullptr);
    lambda_part_kernel<<<dim3(8, NHEADS), 256>>>();
    lambda_comb_kernel<<<NHEADS, 256>>>();
    attn_out_kernel<<<dim3(4, 4, NHEADS), 256>>>(rel_pos);
    gemm_kernel<1><<<dim3(4, 32, BB), 256>>>(out);
}

// round 16
// speedup vs baseline: 1.2531x; 1.0422x over previous
#include <cuda_runtime.h>
#include <cuda_bf16.h>
#include <math.h>
#include <stdint.h>

#define BB 16
#define CC 128
#define HH 64
#define WW 64
#define NN 4096      // HH*WW
#define NHH 8
#define HDD 16
#define NHEADS 128   // BB*NHH
#define OUTC 512

// ---------------- scratch (static device globals; no allocation allowed) ----
__device__ float    g_qkv[BB * 3 * CC * NN];   // 100.7 MB : q|k|v (b, 384, n)
__device__ float    g_pool[BB * CC];
__device__ float    g_pnum[NHEADS * 8 * 256];
__device__ float    g_pden[NHEADS * 8 * 16];
// packed bf16x2 operand planes (hi/lo split), pairs along K(channel)
__device__ uint32_t g_sh[BB * 64 * NN];        // 16.8 MB : CPE output (pairs)
__device__ uint32_t g_sl[BB * 64 * NN];
__device__ uint32_t g_xh[BB * 128 * NN];       // 33.5 MB : cat(r1, src*ca) pairs
__device__ uint32_t g_xl[BB * 128 * NN];
// weights packed in MMA-FRAGMENT order: [mt][kc][mb][gid][tig][w], w=4 contiguous
__device__ uint32_t g_wqh[3 * 8 * 1024],  g_wql[3 * 8 * 1024];    // qkv_w
__device__ uint32_t g_woh[4 * 16 * 1024], g_wol[4 * 16 * 1024];   // out_w

// ---------------------------------------------------------------------------
__device__ __forceinline__ void bf16_split2(float x0, float x1,
                                            uint32_t& hi, uint32_t& lo)
{
    __nv_bfloat16 h0 = __float2bfloat16_rn(x0);
    __nv_bfloat16 h1 = __float2bfloat16_rn(x1);
    __nv_bfloat16 l0 = __float2bfloat16_rn(x0 - __bfloat162float(h0));
    __nv_bfloat16 l1 = __float2bfloat16_rn(x1 - __bfloat162float(h1));
    hi = ((uint32_t)__bfloat16_as_ushort(h1) << 16) | __bfloat16_as_ushort(h0);
    lo = ((uint32_t)__bfloat16_as_ushort(l1) << 16) | __bfloat16_as_ushort(l0);
}

__device__ __forceinline__ void mma_bf16(float* d, const uint32_t* a, const uint32_t* b)
{
    asm volatile(
        "mma.sync.aligned.m16n8k16.row.col.f32.bf16.bf16.f32 "
        "{%0,%1,%2,%3}, {%4,%5,%6,%7}, {%8,%9}, {%0,%1,%2,%3};"
        : "+f"(d[0]), "+f"(d[1]), "+f"(d[2]), "+f"(d[3])
        : "r"(a[0]), "r"(a[1]), "r"(a[2]), "r"(a[3]), "r"(b[0]), "r"(b[1]));
}

__device__ __forceinline__ uint32_t smem_u32(const void* p) {
    uint32_t a;
    asm("{ .reg .u64 t; cvta.to.shared.u64 t, %1; cvt.u32.u64 %0, t; }"
        : "=r"(a) : "l"(p));
    return a;
}
#define CPA16(dst, src) \
    asm volatile("cp.async.cg.shared.global [%0], [%1], 16;" :: "r"(dst), "l"(src) : "memory")
#define CPA_COMMIT() asm volatile("cp.async.commit_group;" ::: "memory")

// ============================================================================
// K1: CPE dw3x3 + residual for a channel PAIR, fused pooling, packed output
// ============================================================================
__global__ __launch_bounds__(256) void cpe_pool_kernel(
    const float* __restrict__ src, const float* __restrict__ cpe_w)
{
    __shared__ float tile[2][HH][WW];   // 32 KB
    __shared__ float2 red[256];

    int cp = blockIdx.x, b = blockIdx.y;
    int c0 = cp * 2;
    int tid = threadIdx.x;
    const float* p0 = src + ((size_t)b * CC + c0) * NN;
    const float* p1 = p0 + NN;

    float s0 = 0.f, s1 = 0.f;
    #pragma unroll 4
    for (int i = tid; i < NN; i += 256) {
        float v0 = p0[i], v1 = p1[i];
        tile[0][i >> 6][i & 63] = v0;
        tile[1][i >> 6][i & 63] = v1;
        s0 += v0; s1 += v1;
    }
    red[tid] = make_float2(s0, s1);
    __syncthreads();
    for (int s = 128; s > 0; s >>= 1) {
        if (tid < s) {
            red[tid].x += red[tid + s].x;
            red[tid].y += red[tid + s].y;
        }
        __syncthreads();
    }
    if (tid == 0) {
        g_pool[b * CC + c0]     = red[0].x * (1.f / (float)NN);
        g_pool[b * CC + c0 + 1] = red[0].y * (1.f / (float)NN);
    }

    float w0[9], w1[9];
    #pragma unroll
    for (int j = 0; j < 9; j++) { w0[j] = cpe_w[c0 * 9 + j]; w1[j] = cpe_w[c0 * 9 + 9 + j]; }

    uint32_t* dh = g_sh + ((size_t)b * 64 + cp) * NN;
    uint32_t* dl = g_sl + ((size_t)b * 64 + cp) * NN;
    for (int i = tid; i < NN; i += 256) {
        int y = i >> 6, x = i & 63;
        float a0 = tile[0][y][x], a1 = tile[1][y][x];
        #pragma unroll
        for (int ky = 0; ky < 3; ky++) {
            int yy = y + ky - 1;
            if ((unsigned)yy >= HH) continue;
            #pragma unroll
            for (int kx = 0; kx < 3; kx++) {
                int xx = x + kx - 1;
                if ((unsigned)xx >= WW) continue;
                a0 += w0[ky * 3 + kx] * tile[0][yy][xx];
                a1 += w1[ky * 3 + kx] * tile[1][yy][xx];
            }
        }
        uint32_t hi, lo;
        bf16_split2(a0, a1, hi, lo);
        dh[i] = hi; dl[i] = lo;
    }
}

// ============================================================================
// K2: pack weights into MMA-fragment order
//   word index within matrix: (((mt*NC + kc)*8 + mb)*8 + gid)*16 + tig*4 + w
//   src: m = mt*128 + mb*16 + gid + (w&1)*8 ; kpair p = kc*8 + tig + (w>>1)*4
// ============================================================================
__global__ __launch_bounds__(256) void pack_w_kernel(
    const float* __restrict__ qkv_w, const float* __restrict__ out_w)
{
    int idx = blockIdx.x * 256 + threadIdx.x;
    if (idx < 3 * 8 * 1024) {           // qkv: NM=3, NC=8
        int w   = idx & 3;
        int tig = (idx >> 2) & 3;
        int gid = (idx >> 4) & 7;
        int mb  = (idx >> 7) & 7;
        int kc  = (idx >> 10) & 7;
        int mt  = idx >> 13;
        int m = mt * 128 + mb * 16 + gid + (w & 1) * 8;
        int p = kc * 8 + tig + (w >> 1) * 4;
        float2 w2 = *(const float2*)&qkv_w[m * 128 + p * 2];
        bf16_split2(w2.x, w2.y, g_wqh[idx], g_wql[idx]);
    }
    int idx2 = idx - 3 * 8 * 1024;
    if (idx2 >= 0 && idx2 < 4 * 16 * 1024) {   // out: NM=4, NC=16
        int w   = idx2 & 3;
        int tig = (idx2 >> 2) & 3;
        int gid = (idx2 >> 4) & 7;
        int mb  = (idx2 >> 7) & 7;
        int kc  = (idx2 >> 10) & 15;
        int mt  = idx2 >> 14;
        int m = mt * 128 + mb * 16 + gid + (w & 1) * 8;
        int p = kc * 8 + tig + (w >> 1) * 4;
        float2 w2 = *(const float2*)&out_w[m * 256 + p * 2];
        bf16_split2(w2.x, w2.y, g_woh[idx2], g_wol[idx2]);
    }
}

// ============================================================================
// K3: pack src*ca into g_x rows 64..127 (ECA sigmoid computed inline)
// ============================================================================
__global__ __launch_bounds__(256) void pack_src_kernel(
    const float* __restrict__ src, const float* __restrict__ conv1d_w)
{
    int cp = blockIdx.x, b = blockIdx.y;
    int tid = threadIdx.x;
    int c0 = cp * 2;
    const float* pp = g_pool + b * CC;
    float wA = conv1d_w[0], wB = conv1d_w[1], wCw = conv1d_w[2];
    float z0 = wA * ((c0 > 0) ? pp[c0 - 1] : 0.f) + wB * pp[c0] + wCw * pp[c0 + 1];
    float z1 = wA * pp[c0] + wB * pp[c0 + 1]
             + wCw * ((c0 + 2 < CC) ? pp[c0 + 2] : 0.f);
    float ca0 = 1.f / (1.f + __expf(-z0));
    float ca1 = 1.f / (1.f + __expf(-z1));

    const float* p0 = src + ((size_t)b * CC + c0) * NN;
    const float* p1 = p0 + NN;
    uint32_t* dh = g_xh + ((size_t)b * 128 + 64 + cp) * NN;
    uint32_t* dl = g_xl + ((size_t)b * 128 + 64 + cp) * NN;

    #pragma unroll
    for (int it = 0; it < 4; it++) {
        int i = (it * 256 + tid) * 4;
        float4 a = *(const float4*)&p0[i];
        float4 c4 = *(const float4*)&p1[i];
        uint4 h, l;
        bf16_split2(a.x * ca0, c4.x * ca1, h.x, l.x);
        bf16_split2(a.y * ca0, c4.y * ca1, h.y, l.y);
        bf16_split2(a.z * ca0, c4.z * ca1, h.z, l.z);
        bf16_split2(a.w * ca0, c4.w * ca1, h.w, l.w);
        *(uint4*)&dh[i] = h;
        *(uint4*)&dl[i] = l;
    }
}

// ============================================================================
// K4: unified split-bf16 GEMM, cp.async double-buffered, fragment-order A
// grid (NM m-tiles [fastest], 32 n-tiles, 16 b)
// ============================================================================
template<int MODE>
__global__ __launch_bounds__(256) void gemm_kernel(float* __restrict__ Cout)
{
    constexpr int K8 = MODE ? 128 : 64;
    constexpr int NC = K8 / 8;

    __shared__ uint32_t sAh[2][1024], sAl[2][1024];      // fragment-order, 4KB each
    __shared__ uint32_t sBh[2][8][132], sBl[2][8][132];

    const uint32_t* Ah = MODE ? g_woh : g_wqh;
    const uint32_t* Al = MODE ? g_wol : g_wql;

    int b  = blockIdx.z;
    int mt = blockIdx.x;            // m fastest -> B strip shared by adjacent CTAs
    int m0 = mt * 128;
    int n0 = blockIdx.y * 128;

    const uint32_t* Bh = (MODE ? g_xh : g_sh) + (size_t)b * K8 * NN;
    const uint32_t* Bl = (MODE ? g_xl : g_sl) + (size_t)b * K8 * NN;
    float* C = MODE ? (Cout + (size_t)b * OUTC * NN)
                    : (g_qkv + (size_t)b * 3 * CC * NN);
    const uint32_t* Abase_h = Ah + (size_t)mt * NC * 1024;
    const uint32_t* Abase_l = Al + (size_t)mt * NC * 1024;

    int tid  = threadIdx.x;
    int warp = tid >> 5, lane = tid & 31;
    int wm = (warp & 1);            // m half (0/1) -> mb offset 4
    int wn = (warp >> 1) * 32;
    int gid = lane >> 2, tig = lane & 3;
    int arow = tid >> 5, aseg = tid & 31;   // B stage mapping: 8 rows x 32 segs

    float acc[16][4];
    #pragma unroll
    for (int i = 0; i < 16; i++)
        #pragma unroll
        for (int j = 0; j < 4; j++) acc[i][j] = 0.f;

    // ---- stage chunk 0
    {
        CPA16(smem_u32(&sAh[0][tid * 4]), Abase_h + tid * 4);
        CPA16(smem_u32(&sAl[0][tid * 4]), Abase_l + tid * 4);
        CPA16(smem_u32(&sBh[0][arow][aseg * 4]), Bh + (size_t)arow * NN + n0 + aseg * 4);
        CPA16(smem_u32(&sBl[0][arow][aseg * 4]), Bl + (size_t)arow * NN + n0 + aseg * 4);
        CPA_COMMIT();
    }

    #pragma unroll 1
    for (int c = 0; c < NC; c++) {
        if (c + 1 < NC) {
            int buf = (c + 1) & 1, k8 = (c + 1) * 8 + arow;
            CPA16(smem_u32(&sAh[buf][tid * 4]), Abase_h + (c + 1) * 1024 + tid * 4);
            CPA16(smem_u32(&sAl[buf][tid * 4]), Abase_l + (c + 1) * 1024 + tid * 4);
            CPA16(smem_u32(&sBh[buf][arow][aseg * 4]), Bh + (size_t)k8 * NN + n0 + aseg * 4);
            CPA16(smem_u32(&sBl[buf][arow][aseg * 4]), Bl + (size_t)k8 * NN + n0 + aseg * 4);
            CPA_COMMIT();
            asm volatile("cp.async.wait_group 1;" ::: "memory");
        } else {
            asm volatile("cp.async.wait_group 0;" ::: "memory");
        }
        __syncthreads();

        int bf = c & 1;
        uint32_t ah[4][4], al[4][4], bh[4][2], bl[4][2];
        #pragma unroll
        for (int am = 0; am < 4; am++) {
            int mb = wm * 4 + am;
            int off = ((mb * 8 + gid) * 4 + tig) * 4;
            uint4 va = *(const uint4*)&sAh[bf][off];
            ah[am][0] = va.x; ah[am][1] = va.y; ah[am][2] = va.z; ah[am][3] = va.w;
            uint4 vb = *(const uint4*)&sAl[bf][off];
            al[am][0] = vb.x; al[am][1] = vb.y; al[am][2] = vb.z; al[am][3] = vb.w;
        }
        #pragma unroll
        for (int an = 0; an < 4; an++) {
            int nc = wn + an * 8 + gid;
            bh[an][0] = sBh[bf][tig][nc];     bl[an][0] = sBl[bf][tig][nc];
            bh[an][1] = sBh[bf][tig + 4][nc]; bl[an][1] = sBl[bf][tig + 4][nc];
        }
        #pragma unroll
        for (int am = 0; am < 4; am++)
            #pragma unroll
            for (int an = 0; an < 4; an++) {
                float* d = acc[am * 4 + an];
                mma_bf16(d, ah[am], bh[an]);
                mma_bf16(d, al[am], bh[an]);
                mma_bf16(d, ah[am], bl[an]);
            }
        __syncthreads();
    }

    #pragma unroll
    for (int am = 0; am < 4; am++)
        #pragma unroll
        for (int an = 0; an < 4; an++) {
            const float* d = acc[am * 4 + an];
            int row = m0 + (wm * 4 + am) * 16 + gid;
            int col = n0 + wn + an * 8 + 2 * tig;
            float* dst = C + (size_t)row * NN + col;
            *(float2*)dst            = make_float2(d[0], d[1]);
            *(float2*)(dst + 8 * NN) = make_float2(d[2], d[3]);
        }
}

// ============================================================================
// K5: partial lambda over N-chunks (no max subtraction; k is O(10) bounded)
// ============================================================================
__global__ __launch_bounds__(256) void lambda_part_kernel()
{
    int ch = blockIdx.x, h = blockIdx.y;
    int b = h >> 3, nh = h & 7;
    int warp = threadIdx.x >> 5, lane = threadIdx.x & 31;
    int i0 = warp * 2;

    const float* kbase = g_qkv + (size_t)(b * 384 + 128 + nh * 16) * NN;
    const float* vbase = g_qkv + (size_t)(b * 384 + 256 + nh * 16) * NN;
    const float* k0p = kbase + (size_t)i0 * NN;
    const float* k1p = k0p + NN;

    float acc0[16], acc1[16], s0 = 0.f, s1 = 0.f;
    #pragma unroll
    for (int o = 0; o < 16; o++) { acc0[o] = 0.f; acc1[o] = 0.f; }

    int nbeg = ch * 512 + lane;
    #pragma unroll 2
    for (int it = 0; it < 16; it++) {
        int n = nbeg + it * 32;
        float p0 = __expf(k0p[n]);
        float p1 = __expf(k1p[n]);
        s0 += p0; s1 += p1;
        #pragma unroll
        for (int o = 0; o < 16; o++) {
            float vv = vbase[(size_t)o * NN + n];
            acc0[o] += p0 * vv;
            acc1[o] += p1 * vv;
        }
    }
    #pragma unroll
    for (int off = 16; off; off >>= 1) {
        s0 += __shfl_xor_sync(0xffffffffu, s0, off);
        s1 += __shfl_xor_sync(0xffffffffu, s1, off);
        #pragma unroll
        for (int o = 0; o < 16; o++) {
            acc0[o] += __shfl_xor_sync(0xffffffffu, acc0[o], off);
            acc1[o] += __shfl_xor_sync(0xffffffffu, acc1[o], off);
        }
    }
    if (lane == 0) {
        float* pn = g_pnum + (size_t)(h * 8 + ch) * 256;
        #pragma unroll
        for (int o = 0; o < 16; o++) {
            pn[i0 * 16 + o]       = acc0[o];
            pn[(i0 + 1) * 16 + o] = acc1[o];
        }
        g_pden[(h * 8 + ch) * 16 + i0]     = s0;
        g_pden[(h * 8 + ch) * 16 + i0 + 1] = s1;
    }
}

// ============================================================================
// K6: result1 = content + q * dwconv5x5(v); lambda combine fused in;
// packed bf16 pair output
// ============================================================================
__global__ __launch_bounds__(256) void attn_out_kernel(const float* __restrict__ rel_pos)
{
    __shared__ float vs[16][20][20];
    __shared__ float ls[16][16];
    __shared__ float rw[16][25];

    int h = blockIdx.z;
    int b = h >> 3, nh = h & 7;
    int x0 = blockIdx.x * 16, y0 = blockIdx.y * 16;

    const float* vbase = g_qkv + (size_t)(b * 384 + 256 + nh * 16) * NN;
    const float* qbase = g_qkv + (size_t)(b * 384 +   0 + nh * 16) * NN;

    int tid = threadIdx.x;
    int tx = tid & 15, ty = tid >> 4;

    // fused lambda combine: t = i*16 + o
    {
        float num = 0.f, den = 0.f;
        int i = tid >> 4;
        #pragma unroll
        for (int ch = 0; ch < 8; ch++) {
            num += g_pnum[(size_t)(h * 8 + ch) * 256 + tid];
            den += g_pden[(h * 8 + ch) * 16 + i];
        }
        ls[tid >> 4][tid & 15] = 0.25f * num / den;
    }
    for (int i = tid; i < 400; i += 256) rw[i / 25][i % 25] = rel_pos[i];

    for (int i = tid; i < 16 * 400; i += 256) {
        int chn = i / 400, r = i % 400;
        int yy = y0 + r / 20 - 2, xx = x0 + (r % 20) - 2;
        float val = 0.f;
        if ((unsigned)yy < HH && (unsigned)xx < WW)
            val = vbase[(size_t)chn * NN + yy * 64 + xx];
        vs[chn][r / 20][r % 20] = val;
    }
    __syncthreads();

    int y = y0 + ty, x = x0 + tx;
    int n = y * 64 + x;

    float q[16];
    #pragma unroll
    for (int i = 0; i < 16; i++) q[i] = qbase[(size_t)i * NN + n];

    float res[16];
    #pragma unroll
    for (int o = 0; o < 16; o++) {
        float cont = 0.f;
        #pragma unroll
        for (int i = 0; i < 16; i++) cont += q[i] * ls[i][o];
        float pos = 0.f;
        #pragma unroll
        for (int ky = 0; ky < 5; ky++)
            #pragma unroll
            for (int kx = 0; kx < 5; kx++)
                pos += rw[o][ky * 5 + kx] * vs[o][ty + ky][tx + kx];
        res[o] = cont + q[o] * pos;
    }

    uint32_t* xh = g_xh + ((size_t)b * 128 + nh * 8) * NN + n;
    uint32_t* xl = g_xl + ((size_t)b * 128 + nh * 8) * NN + n;
    #pragma unroll
    for (int o2 = 0; o2 < 8; o2++) {
        uint32_t hi, lo;
        bf16_split2(res[2 * o2], res[2 * o2 + 1], hi, lo);
        xh[(size_t)o2 * NN] = hi;
        xl[(size_t)o2 * NN] = lo;
    }
}

// ============================================================================
extern "C" void kernel_launch(void* const* d_in, const int* in_sizes, int n_in,
                              void* d_out, int out_size)
{
    const float* src      = (const float*)d_in[0];  // (16,128,64,64)
    const float* cpe_w    = (const float*)d_in[1];  // (128,1,3,3)
    const float* qkv_w    = (const float*)d_in[2];  // (384,128)
    const float* rel_pos  = (const float*)d_in[3];  // (16,5,5)
    const float* conv1d_w = (const float*)d_in[4];  // (3,)
    const float* out_w    = (const float*)d_in[5];  // (512,256)
    float* out = (float*)d_out;                     // (16,512,64,64)

    pack_w_kernel<<<(3 * 8 * 1024 + 4 * 16 * 1024 + 255) / 256, 256>>>(qkv_w, out_w);
    cpe_pool_kernel<<<dim3(64, BB), 256>>>(src, cpe_w);
    pack_src_kernel<<<dim3(64, BB), 256>>>(src, conv1d_w);
    gemm_kernel<0><<<dim3(3, 32, BB), 256>>>(nullptr);
    lambda_part_kernel<<<dim3(8, NHEADS), 256>>>();
    attn_out_kernel<<<dim3(4, 4, NHEADS), 256>>>(rel_pos);
    gemm_kernel<1><<<dim3(4, 32, BB), 256>>>(out);
}